// round 1
// baseline (speedup 1.0000x reference)
#include <cuda_runtime.h>
#include <cstdint>

#define D_MODEL 1024
#define N_HEADS 16
#define D_HEAD  64
#define D_FF    4096
#define BATCH   4
#define SEQ     1024
#define M_TOK   (BATCH*SEQ)   // 4096

// ---------------- scratch (allocation-free: device globals) ----------------
__device__ float g_h  [M_TOK*D_MODEL];
__device__ float g_q  [M_TOK*D_MODEL];
__device__ float g_k  [M_TOK*D_MODEL];
__device__ float g_v  [M_TOK*D_MODEL];
__device__ float g_vT [M_TOK*D_MODEL];
__device__ float g_o1 [M_TOK*D_MODEL];
__device__ float g_h2 [M_TOK*D_MODEL];
__device__ float g_ff [M_TOK*D_FF];

// ---------------- helpers ----------------
__device__ __forceinline__ uint32_t f2tf(float f) {
    uint32_t u;
    asm("cvt.rna.tf32.f32 %0, %1;" : "=r"(u) : "f"(f));
    return u;
}

__device__ __forceinline__ void mma_tf32(float* c, const uint32_t* a, const uint32_t* b) {
    asm volatile(
        "mma.sync.aligned.m16n8k8.row.col.f32.tf32.tf32.f32 "
        "{%0,%1,%2,%3}, {%4,%5,%6,%7}, {%8,%9}, {%0,%1,%2,%3};\n"
        : "+f"(c[0]), "+f"(c[1]), "+f"(c[2]), "+f"(c[3])
        : "r"(a[0]), "r"(a[1]), "r"(a[2]), "r"(a[3]), "r"(b[0]), "r"(b[1]));
}

// ---------------- LayerNorm (unbiased var, /(std+eps)) ----------------
__global__ void ln_kernel(const float* __restrict__ x, const float* __restrict__ g,
                          const float* __restrict__ b, float* __restrict__ out) {
    int row = blockIdx.x;
    int t = threadIdx.x;  // 256 threads, 4 floats each
    const float4* xr = (const float4*)(x + (size_t)row * D_MODEL);
    float4 v = xr[t];
    __shared__ float red[8];

    float s = v.x + v.y + v.z + v.w;
    #pragma unroll
    for (int o = 16; o; o >>= 1) s += __shfl_xor_sync(0xffffffffu, s, o);
    if ((t & 31) == 0) red[t >> 5] = s;
    __syncthreads();
    float tot = red[0]+red[1]+red[2]+red[3]+red[4]+red[5]+red[6]+red[7];
    float mean = tot * (1.0f / D_MODEL);

    float dx = v.x - mean, dy = v.y - mean, dz = v.z - mean, dw = v.w - mean;
    float ss = dx*dx + dy*dy + dz*dz + dw*dw;
    #pragma unroll
    for (int o = 16; o; o >>= 1) ss += __shfl_xor_sync(0xffffffffu, ss, o);
    __syncthreads();
    if ((t & 31) == 0) red[t >> 5] = ss;
    __syncthreads();
    float vtot = red[0]+red[1]+red[2]+red[3]+red[4]+red[5]+red[6]+red[7];
    float inv = 1.0f / (sqrtf(vtot * (1.0f / (D_MODEL - 1))) + 1e-12f);

    float4 g4 = ((const float4*)g)[t];
    float4 b4 = ((const float4*)b)[t];
    float4 o4;
    o4.x = g4.x * dx * inv + b4.x;
    o4.y = g4.y * dy * inv + b4.y;
    o4.z = g4.z * dz * inv + b4.z;
    o4.w = g4.w * dw * inv + b4.w;
    ((float4*)(out + (size_t)row * D_MODEL))[t] = o4;
}

// ---------------- softmax (in-place over rows of length SEQ) ----------------
__global__ void softmax_kernel(float* __restrict__ attn) {
    size_t row = blockIdx.x;
    float4* p = (float4*)(attn + row * SEQ);
    int t = threadIdx.x;
    float4 v = p[t];
    __shared__ float red[8];

    float mx = fmaxf(fmaxf(v.x, v.y), fmaxf(v.z, v.w));
    #pragma unroll
    for (int o = 16; o; o >>= 1) mx = fmaxf(mx, __shfl_xor_sync(0xffffffffu, mx, o));
    if ((t & 31) == 0) red[t >> 5] = mx;
    __syncthreads();
    mx = fmaxf(fmaxf(fmaxf(red[0],red[1]),fmaxf(red[2],red[3])),
               fmaxf(fmaxf(red[4],red[5]),fmaxf(red[6],red[7])));

    v.x = expf(v.x - mx); v.y = expf(v.y - mx);
    v.z = expf(v.z - mx); v.w = expf(v.w - mx);
    float s = v.x + v.y + v.z + v.w;
    #pragma unroll
    for (int o = 16; o; o >>= 1) s += __shfl_xor_sync(0xffffffffu, s, o);
    __syncthreads();
    if ((t & 31) == 0) red[t >> 5] = s;
    __syncthreads();
    float tot = red[0]+red[1]+red[2]+red[3]+red[4]+red[5]+red[6]+red[7];
    float inv = 1.0f / tot;
    v.x *= inv; v.y *= inv; v.z *= inv; v.w *= inv;
    p[t] = v;
}

// ---------------- V transpose: v[b,s,h,d] -> vT[(b*H+h)*64+d][s] ----------------
__global__ void transpose_v(const float* __restrict__ v, float* __restrict__ vT) {
    __shared__ float tile[32][33];
    int bh = blockIdx.z;             // b*H + h
    int b = bh / N_HEADS, h = bh % N_HEADS;
    int s0 = blockIdx.x * 32;
    int d0 = blockIdx.y * 32;
    int tx = threadIdx.x, ty = threadIdx.y;  // 32 x 8
    const float* src = v + ((size_t)b * SEQ) * D_MODEL + h * D_HEAD;
    #pragma unroll
    for (int i = 0; i < 32; i += 8)
        tile[ty + i][tx] = src[(size_t)(s0 + ty + i) * D_MODEL + d0 + tx];
    __syncthreads();
    float* dst = vT + ((size_t)bh * D_HEAD) * SEQ;
    #pragma unroll
    for (int i = 0; i < 32; i += 8)
        dst[(size_t)(d0 + ty + i) * SEQ + s0 + tx] = tile[tx][ty + i];
}

// ---------------- generalized tf32 GEMM: C = scale*(A[M,K] @ B[N,K]^T) (+bias)(+res)(relu) ----------------
#define BM 128
#define BN 128
#define BK 16
#define KS 20   // padded smem row stride (floats): conflict-free for mma lane pattern

__global__ void __launch_bounds__(256)
gemm_tf32(const float* __restrict__ A, const float* __restrict__ B,
          float* __restrict__ C, const float* __restrict__ bias,
          const float* __restrict__ res,
          int M, int N, int K, int lda, int ldb, int ldc,
          float scale, int relu, int zmod,
          long long aLo, long long aHi, long long bLo, long long bHi,
          long long cLo, long long cHi)
{
    int z = blockIdx.z;
    int zlo = z % zmod, zhi = z / zmod;
    A += (size_t)zlo * aLo + (size_t)zhi * aHi;
    B += (size_t)zlo * bLo + (size_t)zhi * bHi;
    size_t coff = (size_t)zlo * cLo + (size_t)zhi * cHi;
    C += coff;
    if (res) res += coff;

    __shared__ uint32_t As[2][BM * KS];
    __shared__ uint32_t Bs[2][BN * KS];

    int tid = threadIdx.x;
    int lane = tid & 31;
    int warp = tid >> 5;
    int wm = (warp & 3) * 32;   // warp m offset (4 warps in M)
    int wn = (warp >> 2) * 64;  // warp n offset (2 warps in N)

    int m0 = blockIdx.y * BM;
    int n0 = blockIdx.x * BN;

    int lr = tid >> 2;          // 0..63
    int lc = (tid & 3) * 4;     // 0,4,8,12

    float acc[2][8][4];
    #pragma unroll
    for (int i = 0; i < 2; i++)
        #pragma unroll
        for (int j = 0; j < 8; j++)
            #pragma unroll
            for (int c = 0; c < 4; c++) acc[i][j][c] = 0.f;

    float4 aReg[2], bReg[2];

    auto loadg = [&](int t) {
        int k0 = t * BK;
        #pragma unroll
        for (int i = 0; i < 2; i++) {
            int r = lr + i * 64;
            int gm = m0 + r;
            if (gm < M) aReg[i] = *(const float4*)(A + (size_t)gm * lda + k0 + lc);
            else        aReg[i] = make_float4(0.f, 0.f, 0.f, 0.f);
            int gn = n0 + r;
            if (gn < N) bReg[i] = *(const float4*)(B + (size_t)gn * ldb + k0 + lc);
            else        bReg[i] = make_float4(0.f, 0.f, 0.f, 0.f);
        }
    };
    auto stores = [&](int buf) {
        #pragma unroll
        for (int i = 0; i < 2; i++) {
            int r = lr + i * 64;
            uint4 ua = make_uint4(f2tf(aReg[i].x), f2tf(aReg[i].y), f2tf(aReg[i].z), f2tf(aReg[i].w));
            *(uint4*)&As[buf][r * KS + lc] = ua;
            uint4 ub = make_uint4(f2tf(bReg[i].x), f2tf(bReg[i].y), f2tf(bReg[i].z), f2tf(bReg[i].w));
            *(uint4*)&Bs[buf][r * KS + lc] = ub;
        }
    };
    auto compute = [&](int buf) {
        #pragma unroll
        for (int kk = 0; kk < 2; ++kk) {
            uint32_t af[2][4];
            #pragma unroll
            for (int mt = 0; mt < 2; ++mt) {
                int row = wm + mt * 16 + (lane >> 2);
                int col = kk * 8 + (lane & 3);
                const uint32_t* p = &As[buf][row * KS + col];
                af[mt][0] = p[0];
                af[mt][1] = p[8 * KS];
                af[mt][2] = p[4];
                af[mt][3] = p[8 * KS + 4];
            }
            uint32_t bf[8][2];
            #pragma unroll
            for (int nt = 0; nt < 8; ++nt) {
                int rowb = wn + nt * 8 + (lane >> 2);
                int col = kk * 8 + (lane & 3);
                const uint32_t* p = &Bs[buf][rowb * KS + col];
                bf[nt][0] = p[0];
                bf[nt][1] = p[4];
            }
            #pragma unroll
            for (int mt = 0; mt < 2; ++mt)
                #pragma unroll
                for (int nt = 0; nt < 8; ++nt)
                    mma_tf32(acc[mt][nt], af[mt], bf[nt]);
        }
    };

    int nk = K / BK;
    loadg(0); stores(0); __syncthreads();
    int buf = 0;
    for (int t = 0; t < nk; ++t) {
        if (t + 1 < nk) loadg(t + 1);
        compute(buf);
        if (t + 1 < nk) { stores(buf ^ 1); __syncthreads(); }
        buf ^= 1;
    }

    // epilogue
    #pragma unroll
    for (int mt = 0; mt < 2; ++mt) {
        #pragma unroll
        for (int nt = 0; nt < 8; ++nt) {
            int rbase = m0 + wm + mt * 16 + (lane >> 2);
            int cbase = n0 + wn + nt * 8 + (lane & 3) * 2;
            #pragma unroll
            for (int c = 0; c < 4; ++c) {
                int rr = rbase + (c >> 1) * 8;
                int cc = cbase + (c & 1);
                if (rr < M && cc < N) {
                    float val = acc[mt][nt][c] * scale;
                    if (bias) val += bias[cc];
                    if (res)  val += res[(size_t)rr * ldc + cc];
                    if (relu) val = fmaxf(val, 0.f);
                    C[(size_t)rr * ldc + cc] = val;
                }
            }
        }
    }
}

// ---------------- launch ----------------
extern "C" void kernel_launch(void* const* d_in, const int* in_sizes, int n_in,
                              void* d_out, int out_size) {
    const float* x     = (const float*)d_in[0];
    const float* ln1_g = (const float*)d_in[1];
    const float* ln1_b = (const float*)d_in[2];
    const float* wq    = (const float*)d_in[3];
    const float* bq    = (const float*)d_in[4];
    const float* wk    = (const float*)d_in[5];
    const float* bk    = (const float*)d_in[6];
    const float* wv    = (const float*)d_in[7];
    const float* bv    = (const float*)d_in[8];
    const float* ln2_g = (const float*)d_in[9];
    const float* ln2_b = (const float*)d_in[10];
    const float* w1    = (const float*)d_in[11];
    const float* b1    = (const float*)d_in[12];
    const float* w2    = (const float*)d_in[13];
    const float* b2    = (const float*)d_in[14];

    float* out  = (float*)d_out;
    float* attn = out + (size_t)BATCH * SEQ * D_MODEL;

    float *h, *q, *k, *v, *vT, *o1, *h2, *ff;
    cudaGetSymbolAddress((void**)&h,  g_h);
    cudaGetSymbolAddress((void**)&q,  g_q);
    cudaGetSymbolAddress((void**)&k,  g_k);
    cudaGetSymbolAddress((void**)&v,  g_v);
    cudaGetSymbolAddress((void**)&vT, g_vT);
    cudaGetSymbolAddress((void**)&o1, g_o1);
    cudaGetSymbolAddress((void**)&h2, g_h2);
    cudaGetSymbolAddress((void**)&ff, g_ff);

    dim3 blk(256);

    // 1) LN1
    ln_kernel<<<M_TOK, 256>>>(x, ln1_g, ln1_b, h);

    // 2) Q, K, V projections: [4096,1024] x [1024,1024]^T
    gemm_tf32<<<dim3(8, 32, 1), blk>>>(h, wq, q, bq, nullptr,
        M_TOK, D_MODEL, D_MODEL, D_MODEL, D_MODEL, D_MODEL, 1.f, 0, 1, 0,0,0,0,0,0);
    gemm_tf32<<<dim3(8, 32, 1), blk>>>(h, wk, k, bk, nullptr,
        M_TOK, D_MODEL, D_MODEL, D_MODEL, D_MODEL, D_MODEL, 1.f, 0, 1, 0,0,0,0,0,0);
    gemm_tf32<<<dim3(8, 32, 1), blk>>>(h, wv, v, bv, nullptr,
        M_TOK, D_MODEL, D_MODEL, D_MODEL, D_MODEL, D_MODEL, 1.f, 0, 1, 0,0,0,0,0,0);

    // 3) V transpose for ctx GEMM (B operand must be [n][k] = [d][s])
    transpose_v<<<dim3(32, 2, BATCH * N_HEADS), dim3(32, 8)>>>(v, vT);

    // 4) scores = q @ k^T / 8, batched over z = h*B + b, written straight to attn output
    gemm_tf32<<<dim3(8, 8, N_HEADS * BATCH), blk>>>(q, k, attn, nullptr, nullptr,
        SEQ, SEQ, D_HEAD, D_MODEL, D_MODEL, SEQ, 0.125f, 0, BATCH,
        (long long)SEQ * D_MODEL, 64,
        (long long)SEQ * D_MODEL, 64,
        (long long)SEQ * SEQ, (long long)BATCH * SEQ * SEQ);

    // 5) softmax in place (rows of attn)
    softmax_kernel<<<N_HEADS * BATCH * SEQ, 256>>>(attn);

    // 6) ctx = attn @ v  (+ residual x), batched over z = h*B + b
    gemm_tf32<<<dim3(1, 8, N_HEADS * BATCH), blk>>>(attn, vT, o1, nullptr, x,
        SEQ, D_HEAD, SEQ, SEQ, SEQ, D_MODEL, 1.f, 0, BATCH,
        (long long)SEQ * SEQ, (long long)BATCH * SEQ * SEQ,
        (long long)N_HEADS * D_HEAD * SEQ, (long long)D_HEAD * SEQ,
        (long long)SEQ * D_MODEL, 64);

    // 7) LN2
    ln_kernel<<<M_TOK, 256>>>(o1, ln2_g, ln2_b, h2);

    // 8) FFN1: relu(h2 @ w1^T + b1)
    gemm_tf32<<<dim3(32, 32, 1), blk>>>(h2, w1, ff, b1, nullptr,
        M_TOK, D_FF, D_MODEL, D_MODEL, D_MODEL, D_FF, 1.f, 1, 1, 0,0,0,0,0,0);

    // 9) FFN2: ff @ w2^T + b2 + o1  -> final out
    gemm_tf32<<<dim3(8, 32, 1), blk>>>(ff, w2, out, b2, o1,
        M_TOK, D_MODEL, D_FF, D_FF, D_FF, D_MODEL, 1.f, 0, 1, 0,0,0,0,0,0);
}

// round 2
// speedup vs baseline: 1.0073x; 1.0073x over previous
#include <cuda_runtime.h>
#include <cstdint>

#define D_MODEL 1024
#define N_HEADS 16
#define D_HEAD  64
#define D_FF    4096
#define BATCH   4
#define SEQ     1024
#define M_TOK   (BATCH*SEQ)   // 4096

// ---------------- scratch (allocation-free: device globals) ----------------
__device__ float g_h  [M_TOK*D_MODEL];
__device__ float g_q  [M_TOK*D_MODEL];
__device__ float g_k  [M_TOK*D_MODEL];
__device__ float g_v  [M_TOK*D_MODEL];
__device__ float g_vT [M_TOK*D_MODEL];
__device__ float g_o1 [M_TOK*D_MODEL];
__device__ float g_h2 [M_TOK*D_MODEL];
__device__ float g_ff [M_TOK*D_FF];

// ---------------- helpers ----------------
__device__ __forceinline__ uint32_t f2tf(float f) {
    uint32_t u;
    asm("cvt.rna.tf32.f32 %0, %1;" : "=r"(u) : "f"(f));
    return u;
}

__device__ __forceinline__ void mma_tf32(float* c, const uint32_t* a, const uint32_t* b) {
    asm volatile(
        "mma.sync.aligned.m16n8k8.row.col.f32.tf32.tf32.f32 "
        "{%0,%1,%2,%3}, {%4,%5,%6,%7}, {%8,%9}, {%0,%1,%2,%3};\n"
        : "+f"(c[0]), "+f"(c[1]), "+f"(c[2]), "+f"(c[3])
        : "r"(a[0]), "r"(a[1]), "r"(a[2]), "r"(a[3]), "r"(b[0]), "r"(b[1]));
}

// ---------------- LayerNorm (unbiased var, /(std+eps)) ----------------
__global__ void ln_kernel(const float* __restrict__ x, const float* __restrict__ g,
                          const float* __restrict__ b, float* __restrict__ out) {
    int row = blockIdx.x;
    int t = threadIdx.x;  // 256 threads, 4 floats each
    const float4* xr = (const float4*)(x + (size_t)row * D_MODEL);
    float4 v = xr[t];
    __shared__ float red[8];

    float s = v.x + v.y + v.z + v.w;
    #pragma unroll
    for (int o = 16; o; o >>= 1) s += __shfl_xor_sync(0xffffffffu, s, o);
    if ((t & 31) == 0) red[t >> 5] = s;
    __syncthreads();
    float tot = red[0]+red[1]+red[2]+red[3]+red[4]+red[5]+red[6]+red[7];
    float mean = tot * (1.0f / D_MODEL);

    float dx = v.x - mean, dy = v.y - mean, dz = v.z - mean, dw = v.w - mean;
    float ss = dx*dx + dy*dy + dz*dz + dw*dw;
    #pragma unroll
    for (int o = 16; o; o >>= 1) ss += __shfl_xor_sync(0xffffffffu, ss, o);
    __syncthreads();
    if ((t & 31) == 0) red[t >> 5] = ss;
    __syncthreads();
    float vtot = red[0]+red[1]+red[2]+red[3]+red[4]+red[5]+red[6]+red[7];
    float inv = 1.0f / (sqrtf(vtot * (1.0f / (D_MODEL - 1))) + 1e-12f);

    float4 g4 = ((const float4*)g)[t];
    float4 b4 = ((const float4*)b)[t];
    float4 o4;
    o4.x = g4.x * dx * inv + b4.x;
    o4.y = g4.y * dy * inv + b4.y;
    o4.z = g4.z * dz * inv + b4.z;
    o4.w = g4.w * dw * inv + b4.w;
    ((float4*)(out + (size_t)row * D_MODEL))[t] = o4;
}

// ---------------- softmax (in-place over rows of length SEQ) ----------------
__global__ void softmax_kernel(float* __restrict__ attn) {
    size_t row = blockIdx.x;
    float4* p = (float4*)(attn + row * SEQ);
    int t = threadIdx.x;
    float4 v = p[t];
    __shared__ float red[8];

    float mx = fmaxf(fmaxf(v.x, v.y), fmaxf(v.z, v.w));
    #pragma unroll
    for (int o = 16; o; o >>= 1) mx = fmaxf(mx, __shfl_xor_sync(0xffffffffu, mx, o));
    if ((t & 31) == 0) red[t >> 5] = mx;
    __syncthreads();
    mx = fmaxf(fmaxf(fmaxf(red[0],red[1]),fmaxf(red[2],red[3])),
               fmaxf(fmaxf(red[4],red[5]),fmaxf(red[6],red[7])));

    v.x = expf(v.x - mx); v.y = expf(v.y - mx);
    v.z = expf(v.z - mx); v.w = expf(v.w - mx);
    float s = v.x + v.y + v.z + v.w;
    #pragma unroll
    for (int o = 16; o; o >>= 1) s += __shfl_xor_sync(0xffffffffu, s, o);
    __syncthreads();
    if ((t & 31) == 0) red[t >> 5] = s;
    __syncthreads();
    float tot = red[0]+red[1]+red[2]+red[3]+red[4]+red[5]+red[6]+red[7];
    float inv = 1.0f / tot;
    v.x *= inv; v.y *= inv; v.z *= inv; v.w *= inv;
    p[t] = v;
}

// ---------------- V transpose: v[b,s,h,d] -> vT[(b*H+h)*64+d][s] ----------------
__global__ void transpose_v(const float* __restrict__ v, float* __restrict__ vT) {
    __shared__ float tile[32][33];
    int bh = blockIdx.z;             // b*H + h
    int b = bh / N_HEADS, h = bh % N_HEADS;
    int s0 = blockIdx.x * 32;
    int d0 = blockIdx.y * 32;
    int tx = threadIdx.x, ty = threadIdx.y;  // 32 x 8
    const float* src = v + ((size_t)b * SEQ) * D_MODEL + h * D_HEAD;
    #pragma unroll
    for (int i = 0; i < 32; i += 8)
        tile[ty + i][tx] = src[(size_t)(s0 + ty + i) * D_MODEL + d0 + tx];
    __syncthreads();
    float* dst = vT + ((size_t)bh * D_HEAD) * SEQ;
    #pragma unroll
    for (int i = 0; i < 32; i += 8)
        dst[(size_t)(d0 + ty + i) * SEQ + s0 + tx] = tile[tx][ty + i];
}

// ---------------- generalized tf32 GEMM: C = scale*(A[M,K] @ B[N,K]^T) (+bias)(+res)(relu) ----------------
#define BM 128
#define BN 128
#define BK 16
#define KS 20   // padded smem row stride (floats): conflict-free for mma lane pattern

__global__ void __launch_bounds__(256)
gemm_tf32(const float* __restrict__ A, const float* __restrict__ B,
          float* __restrict__ C, const float* __restrict__ bias,
          const float* __restrict__ res,
          int M, int N, int K, int lda, int ldb, int ldc,
          float scale, int relu, int zmod,
          long long aLo, long long aHi, long long bLo, long long bHi,
          long long cLo, long long cHi)
{
    int z = blockIdx.z;
    int zlo = z % zmod, zhi = z / zmod;
    A += (size_t)zlo * aLo + (size_t)zhi * aHi;
    B += (size_t)zlo * bLo + (size_t)zhi * bHi;
    size_t coff = (size_t)zlo * cLo + (size_t)zhi * cHi;
    C += coff;
    if (res) res += coff;

    __shared__ uint32_t As[2][BM * KS];
    __shared__ uint32_t Bs[2][BN * KS];

    int tid = threadIdx.x;
    int lane = tid & 31;
    int warp = tid >> 5;
    int wm = (warp & 3) * 32;   // warp m offset (4 warps in M)
    int wn = (warp >> 2) * 64;  // warp n offset (2 warps in N)

    int m0 = blockIdx.y * BM;
    int n0 = blockIdx.x * BN;

    int lr = tid >> 2;          // 0..63
    int lc = (tid & 3) * 4;     // 0,4,8,12

    float acc[2][8][4];
    #pragma unroll
    for (int i = 0; i < 2; i++)
        #pragma unroll
        for (int j = 0; j < 8; j++)
            #pragma unroll
            for (int c = 0; c < 4; c++) acc[i][j][c] = 0.f;

    float4 aReg[2], bReg[2];

    auto loadg = [&](int t) {
        int k0 = t * BK;
        #pragma unroll
        for (int i = 0; i < 2; i++) {
            int r = lr + i * 64;
            int gm = m0 + r;
            if (gm < M) aReg[i] = *(const float4*)(A + (size_t)gm * lda + k0 + lc);
            else        aReg[i] = make_float4(0.f, 0.f, 0.f, 0.f);
            int gn = n0 + r;
            if (gn < N) bReg[i] = *(const float4*)(B + (size_t)gn * ldb + k0 + lc);
            else        bReg[i] = make_float4(0.f, 0.f, 0.f, 0.f);
        }
    };
    auto stores = [&](int buf) {
        #pragma unroll
        for (int i = 0; i < 2; i++) {
            int r = lr + i * 64;
            uint4 ua = make_uint4(f2tf(aReg[i].x), f2tf(aReg[i].y), f2tf(aReg[i].z), f2tf(aReg[i].w));
            *(uint4*)&As[buf][r * KS + lc] = ua;
            uint4 ub = make_uint4(f2tf(bReg[i].x), f2tf(bReg[i].y), f2tf(bReg[i].z), f2tf(bReg[i].w));
            *(uint4*)&Bs[buf][r * KS + lc] = ub;
        }
    };
    auto compute = [&](int buf) {
        #pragma unroll
        for (int kk = 0; kk < 2; ++kk) {
            uint32_t af[2][4];
            #pragma unroll
            for (int mt = 0; mt < 2; ++mt) {
                int row = wm + mt * 16 + (lane >> 2);
                int col = kk * 8 + (lane & 3);
                const uint32_t* p = &As[buf][row * KS + col];
                af[mt][0] = p[0];
                af[mt][1] = p[8 * KS];
                af[mt][2] = p[4];
                af[mt][3] = p[8 * KS + 4];
            }
            uint32_t bf[8][2];
            #pragma unroll
            for (int nt = 0; nt < 8; ++nt) {
                int rowb = wn + nt * 8 + (lane >> 2);
                int col = kk * 8 + (lane & 3);
                const uint32_t* p = &Bs[buf][rowb * KS + col];
                bf[nt][0] = p[0];
                bf[nt][1] = p[4];
            }
            #pragma unroll
            for (int mt = 0; mt < 2; ++mt)
                #pragma unroll
                for (int nt = 0; nt < 8; ++nt)
                    mma_tf32(acc[mt][nt], af[mt], bf[nt]);
        }
    };

    int nk = K / BK;
    loadg(0); stores(0); __syncthreads();
    int buf = 0;
    for (int t = 0; t < nk; ++t) {
        if (t + 1 < nk) loadg(t + 1);
        compute(buf);
        if (t + 1 < nk) { stores(buf ^ 1); __syncthreads(); }
        buf ^= 1;
    }

    // epilogue
    #pragma unroll
    for (int mt = 0; mt < 2; ++mt) {
        #pragma unroll
        for (int nt = 0; nt < 8; ++nt) {
            int rbase = m0 + wm + mt * 16 + (lane >> 2);
            int cbase = n0 + wn + nt * 8 + (lane & 3) * 2;
            #pragma unroll
            for (int c = 0; c < 4; ++c) {
                int rr = rbase + (c >> 1) * 8;
                int cc = cbase + (c & 1);
                if (rr < M && cc < N) {
                    float val = acc[mt][nt][c] * scale;
                    if (bias) val += bias[cc];
                    if (res)  val += res[(size_t)rr * ldc + cc];
                    if (relu) val = fmaxf(val, 0.f);
                    C[(size_t)rr * ldc + cc] = val;
                }
            }
        }
    }
}

// ---------------- launch ----------------
extern "C" void kernel_launch(void* const* d_in, const int* in_sizes, int n_in,
                              void* d_out, int out_size) {
    const float* x     = (const float*)d_in[0];
    const float* ln1_g = (const float*)d_in[1];
    const float* ln1_b = (const float*)d_in[2];
    const float* wq    = (const float*)d_in[3];
    const float* bq    = (const float*)d_in[4];
    const float* wk    = (const float*)d_in[5];
    const float* bk    = (const float*)d_in[6];
    const float* wv    = (const float*)d_in[7];
    const float* bv    = (const float*)d_in[8];
    const float* ln2_g = (const float*)d_in[9];
    const float* ln2_b = (const float*)d_in[10];
    const float* w1    = (const float*)d_in[11];
    const float* b1    = (const float*)d_in[12];
    const float* w2    = (const float*)d_in[13];
    const float* b2    = (const float*)d_in[14];

    float* out  = (float*)d_out;
    float* attn = out + (size_t)BATCH * SEQ * D_MODEL;

    float *h, *q, *k, *v, *vT, *o1, *h2, *ff;
    cudaGetSymbolAddress((void**)&h,  g_h);
    cudaGetSymbolAddress((void**)&q,  g_q);
    cudaGetSymbolAddress((void**)&k,  g_k);
    cudaGetSymbolAddress((void**)&v,  g_v);
    cudaGetSymbolAddress((void**)&vT, g_vT);
    cudaGetSymbolAddress((void**)&o1, g_o1);
    cudaGetSymbolAddress((void**)&h2, g_h2);
    cudaGetSymbolAddress((void**)&ff, g_ff);

    dim3 blk(256);

    // 1) LN1
    ln_kernel<<<M_TOK, 256>>>(x, ln1_g, ln1_b, h);

    // 2) Q, K, V projections: [4096,1024] x [1024,1024]^T
    gemm_tf32<<<dim3(8, 32, 1), blk>>>(h, wq, q, bq, nullptr,
        M_TOK, D_MODEL, D_MODEL, D_MODEL, D_MODEL, D_MODEL, 1.f, 0, 1, 0,0,0,0,0,0);
    gemm_tf32<<<dim3(8, 32, 1), blk>>>(h, wk, k, bk, nullptr,
        M_TOK, D_MODEL, D_MODEL, D_MODEL, D_MODEL, D_MODEL, 1.f, 0, 1, 0,0,0,0,0,0);
    gemm_tf32<<<dim3(8, 32, 1), blk>>>(h, wv, v, bv, nullptr,
        M_TOK, D_MODEL, D_MODEL, D_MODEL, D_MODEL, D_MODEL, 1.f, 0, 1, 0,0,0,0,0,0);

    // 3) V transpose for ctx GEMM (B operand must be [n][k] = [d][s])
    transpose_v<<<dim3(32, 2, BATCH * N_HEADS), dim3(32, 8)>>>(v, vT);

    // 4) scores = q @ k^T / 8, batched over z = h*B + b, written straight to attn output
    gemm_tf32<<<dim3(8, 8, N_HEADS * BATCH), blk>>>(q, k, attn, nullptr, nullptr,
        SEQ, SEQ, D_HEAD, D_MODEL, D_MODEL, SEQ, 0.125f, 0, BATCH,
        (long long)SEQ * D_MODEL, 64,
        (long long)SEQ * D_MODEL, 64,
        (long long)SEQ * SEQ, (long long)BATCH * SEQ * SEQ);

    // 5) softmax in place (rows of attn)
    softmax_kernel<<<N_HEADS * BATCH * SEQ, 256>>>(attn);

    // 6) ctx = attn @ v  (+ residual x), batched over z = h*B + b
    gemm_tf32<<<dim3(1, 8, N_HEADS * BATCH), blk>>>(attn, vT, o1, nullptr, x,
        SEQ, D_HEAD, SEQ, SEQ, SEQ, D_MODEL, 1.f, 0, BATCH,
        (long long)SEQ * SEQ, (long long)BATCH * SEQ * SEQ,
        (long long)N_HEADS * D_HEAD * SEQ, (long long)D_HEAD * SEQ,
        (long long)SEQ * D_MODEL, 64);

    // 7) LN2
    ln_kernel<<<M_TOK, 256>>>(o1, ln2_g, ln2_b, h2);

    // 8) FFN1: relu(h2 @ w1^T + b1)
    gemm_tf32<<<dim3(32, 32, 1), blk>>>(h2, w1, ff, b1, nullptr,
        M_TOK, D_FF, D_MODEL, D_MODEL, D_MODEL, D_FF, 1.f, 1, 1, 0,0,0,0,0,0);

    // 9) FFN2: ff @ w2^T + b2 + o1  -> final out
    gemm_tf32<<<dim3(8, 32, 1), blk>>>(ff, w2, out, b2, o1,
        M_TOK, D_MODEL, D_FF, D_FF, D_FF, D_MODEL, 1.f, 0, 1, 0,0,0,0,0,0);
}